// round 12
// baseline (speedup 1.0000x reference)
#include <cuda_runtime.h>
#include <cuda_fp16.h>
#include <math.h>

#define BN    8192
#define HID   128
#define NE    262144
#define NRBF  64
#define NBLK  4
#define TLEN  512
#define RCUTF 6.0f
#define GAMMAF (10.0f/36.0f)
#define NT    128          // threads per GEMM block
#define TR    32           // rows per GEMM tile
#define EBLK  148          // persistent edge blocks (one per SM)
#define ETHR  512          // threads per edge block

// ---- scratch (device globals: allocation-free) ----
__device__ float  g_h[BN * HID];
__device__ __half g_x[BN * HID];                // fp16 x = h @ lin_in
__device__ float  g_agg[BN * HID];
__device__ int4   g_ep[NE];                     // packed edge: {u_bits, src, dst, 0}
__device__ __half g_tab[NBLK * TLEN * HID];     // 512 KB total; 128 KB per block

__device__ __forceinline__ float silu_f(float v) { return v / (1.0f + expf(-v)); }

// ---------------------------------------------------------------- distances -> packed edge records
__global__ void k_dist(const int* __restrict__ ei, const float* __restrict__ pos) {
    int e = blockIdx.x * blockDim.x + threadIdx.x;
    if (e >= NE) return;
    int s = ei[e], d = ei[NE + e];
    float dx = pos[3*s]   - pos[3*d];
    float dy = pos[3*s+1] - pos[3*d+1];
    float dz = pos[3*s+2] - pos[3*d+2];
    float dd = sqrtf(dx*dx + dy*dy + dz*dz);
    dd = fminf(dd, RCUTF);
    float u = dd * ((float)(TLEN - 1) / RCUTF);
    g_ep[e] = make_int4(__float_as_int(u), s, d, 0);
}

// ================================================================
// GEMM tiles: 32 rows x 128 cols, 128 threads, thread tile 4x8 (proven ILP shape).
// ================================================================

#define GEMM_BODY4(SRC, KDIM)                                             \
    int cg = tid & 15, rg = tid >> 4;                                     \
    float acc[4][8];                                                      \
    _Pragma("unroll")                                                     \
    for (int r = 0; r < 4; r++)                                           \
        _Pragma("unroll")                                                 \
        for (int c = 0; c < 8; c++) acc[r][c] = 0.0f;                     \
    _Pragma("unroll 4")                                                   \
    for (int k = 0; k < KDIM; k++) {                                      \
        float4 w0 = ((const float4*)(Ws + k * 128))[cg * 2];              \
        float4 w1v = ((const float4*)(Ws + k * 128))[cg * 2 + 1];         \
        _Pragma("unroll")                                                 \
        for (int r = 0; r < 4; r++) {                                     \
            float a = SRC[(rg * 4 + r) * KDIM + k];                       \
            acc[r][0] += a * w0.x;  acc[r][1] += a * w0.y;                \
            acc[r][2] += a * w0.z;  acc[r][3] += a * w0.w;                \
            acc[r][4] += a * w1v.x; acc[r][5] += a * w1v.y;               \
            acc[r][6] += a * w1v.z; acc[r][7] += a * w1v.w;               \
        }                                                                 \
    }

// ---------------------------------------------------------------- tables: w_i(d), fp16 out
// grid (TLEN/32, NBLK), block 128; smem rbf[32*64] + act[32*128] + Ws[128*128] = 88 KB
__global__ void __launch_bounds__(NT, 2)
k_table_f(const float* __restrict__ w1, const float* __restrict__ b1,
          const float* __restrict__ w2, const float* __restrict__ b2) {
    extern __shared__ float sm[];
    float* rbfs = sm;                    // 32*64
    float* act  = sm + 32*64;            // 32*128
    float* Ws   = sm + 32*64 + 32*128;   // 128*128
    int tid = threadIdx.x;
    int blk = blockIdx.y;
    int t0  = blockIdx.x * TR;
    const float DSTEP = RCUTF / (float)(TLEN - 1);
    const float CSTEP = RCUTF / (float)(NRBF - 1);

    for (int i = tid; i < TR * 64; i += NT) {
        int row = i >> 6, c = i & 63;
        float d = (float)(t0 + row) * DSTEP;
        float u = d - (float)c * CSTEP;
        rbfs[i] = expf(-GAMMAF * u * u);
    }
    {
        const float4* W4 = (const float4*)(w1 + blk * NRBF * HID);
        float4* Ws4 = (float4*)Ws;
        for (int i = tid; i < NRBF * 32; i += NT) Ws4[i] = W4[i];
    }
    __syncthreads();

    {
        GEMM_BODY4(rbfs, NRBF)
        float bb[8];
        #pragma unroll
        for (int c = 0; c < 8; c++) bb[c] = __ldg(&b1[blk * HID + cg * 8 + c]);
        #pragma unroll
        for (int r = 0; r < 4; r++)
            #pragma unroll
            for (int c = 0; c < 8; c++)
                act[(rg * 4 + r) * 128 + cg * 8 + c] = silu_f(acc[r][c] + bb[c]);
    }
    __syncthreads();
    {
        const float4* W4 = (const float4*)(w2 + blk * HID * HID);
        float4* Ws4 = (float4*)Ws;
        for (int i = tid; i < HID * 32; i += NT) Ws4[i] = W4[i];
    }
    __syncthreads();
    {
        GEMM_BODY4(act, HID)
        float bb[8];
        #pragma unroll
        for (int c = 0; c < 8; c++) bb[c] = __ldg(&b2[blk * HID + cg * 8 + c]);
        #pragma unroll
        for (int r = 0; r < 4; r++) {
            __half2* dst = (__half2*)(g_tab + (size_t)(blk * TLEN + t0 + rg * 4 + r) * HID + cg * 8);
            dst[0] = __floats2half2_rn(acc[r][0] + bb[0], acc[r][1] + bb[1]);
            dst[1] = __floats2half2_rn(acc[r][2] + bb[2], acc[r][3] + bb[3]);
            dst[2] = __floats2half2_rn(acc[r][4] + bb[4], acc[r][5] + bb[5]);
            dst[3] = __floats2half2_rn(acc[r][6] + bb[6], acc[r][7] + bb[7]);
        }
    }
}

// ---------------------------------------------------------------- embed + x = h @ lin_in[0]; zero agg
// grid BN/32, block 128; smem hs[32*128] + Ws[128*128] = 80 KB
__global__ void __launch_bounds__(NT, 2)
k_xgemm_f(const float* __restrict__ W, const int* __restrict__ Z,
          const float* __restrict__ embed_w) {
    extern __shared__ float sm[];
    float* hs = sm;                   // 32*128
    float* Ws = sm + TR * 128;        // 128*128
    int tid = threadIdx.x;
    int row0 = blockIdx.x * TR;
    {
        float4* d4 = (float4*)hs;
        float4* h4 = (float4*)(g_h + (size_t)row0 * HID);
        for (int i = tid; i < TR * 32; i += NT) {
            int z = __ldg(&Z[row0 + (i >> 5)]);
            float4 v = __ldg(((const float4*)(embed_w + (size_t)z * HID)) + (i & 31));
            d4[i] = v;
            h4[i] = v;
        }
        const float4* W4 = (const float4*)W;
        float4* Ws4 = (float4*)Ws;
        for (int i = tid; i < HID * 32; i += NT) Ws4[i] = W4[i];
    }
    __syncthreads();
    GEMM_BODY4(hs, HID)
    #pragma unroll
    for (int r = 0; r < 4; r++) {
        __half2* dst = (__half2*)(g_x + (size_t)(row0 + rg * 4 + r) * HID + cg * 8);
        dst[0] = __floats2half2_rn(acc[r][0], acc[r][1]);
        dst[1] = __floats2half2_rn(acc[r][2], acc[r][3]);
        dst[2] = __floats2half2_rn(acc[r][4], acc[r][5]);
        dst[3] = __floats2half2_rn(acc[r][6], acc[r][7]);
    }
    float4 z4 = {0.f, 0.f, 0.f, 0.f};
    float4* ag4 = (float4*)(g_agg + (size_t)row0 * HID);
    for (int i = tid; i < TR * 32; i += NT) ag4[i] = z4;
}

// ---------------------------------------------------------------- edge scatter: smem-staged table
// 148 persistent blocks x 512 threads; table (128 KB) staged to smem; warp per edge, 2-edge unroll
__device__ __forceinline__ void edge_do(const uint2* __restrict__ tabs, int lane, int4 ep) {
    float u = __int_as_float(ep.x);
    int i0 = (int)u;
    if (i0 > TLEN - 2) i0 = TLEN - 2;
    float f = u - (float)i0;
    uint2 ua = tabs[i0 * 32 + lane];
    uint2 ub = tabs[(i0 + 1) * 32 + lane];
    float2 a01 = __half22float2(*reinterpret_cast<const __half2*>(&ua.x));
    float2 a23 = __half22float2(*reinterpret_cast<const __half2*>(&ua.y));
    float2 b01 = __half22float2(*reinterpret_cast<const __half2*>(&ub.x));
    float2 b23 = __half22float2(*reinterpret_cast<const __half2*>(&ub.y));
    uint2 ux = __ldcg((const uint2*)(g_x + (size_t)ep.y * HID) + lane);
    float2 x01 = __half22float2(*reinterpret_cast<const __half2*>(&ux.x));
    float2 x23 = __half22float2(*reinterpret_cast<const __half2*>(&ux.y));
    float m0 = (a01.x + f * (b01.x - a01.x)) * x01.x;
    float m1 = (a01.y + f * (b01.y - a01.y)) * x01.y;
    float m2 = (a23.x + f * (b23.x - a23.x)) * x23.x;
    float m3 = (a23.y + f * (b23.y - a23.y)) * x23.y;
    float* ag = g_agg + (size_t)ep.z * HID + lane * 4;
    asm volatile("red.global.add.v4.f32 [%0], {%1, %2, %3, %4};"
                 :: "l"(ag), "f"(m0), "f"(m1), "f"(m2), "f"(m3) : "memory");
}

__global__ void __launch_bounds__(ETHR, 1)
k_edge_sm(int blk, int chunk) {
    extern __shared__ __align__(16) char smc[];
    uint2* tabs = (uint2*)smc;                    // TLEN rows x 32 uint2 = 128 KB
    {   // stage table for this interaction block
        const float4* src = (const float4*)(g_tab + (size_t)blk * TLEN * HID);
        float4* dst = (float4*)smc;
        for (int i = threadIdx.x; i < TLEN * HID * 2 / 16; i += ETHR) dst[i] = src[i];
    }
    __syncthreads();
    int warp = threadIdx.x >> 5, lane = threadIdx.x & 31;
    int e0 = blockIdx.x * chunk;
    int e1 = e0 + chunk; if (e1 > NE) e1 = NE;
    int e = e0 + warp;
    for (; e + 16 < e1; e += 32) {
        int4 ep0 = __ldcs(&g_ep[e]);
        int4 ep1 = __ldcs(&g_ep[e + 16]);
        edge_do(tabs, lane, ep0);
        edge_do(tabs, lane, ep1);
    }
    if (e < e1) {
        int4 ep0 = __ldcs(&g_ep[e]);
        edge_do(tabs, lane, ep0);
    }
}

// ---------------------------------------------------------------- fused node MLP + residual + LN
//   + (if hasNext) x = h_new @ lin_in[next], re-zero agg
// grid BN/32, block 128; smem ins[32*128] + act[32*128] + Ws[128*128] = 96 KB
__global__ void __launch_bounds__(NT, 2)
k_node_f(const float* __restrict__ W1, const float* __restrict__ B1,
         const float* __restrict__ W2, const float* __restrict__ B2,
         const float* __restrict__ G,  const float* __restrict__ Bt,
         const float* __restrict__ WlinNext, int hasNext) {
    extern __shared__ float sm[];
    float* ins = sm;                    // 32*128: agg -> y -> h_new
    float* act = sm + TR * 128;         // 32*128
    float* Ws  = sm + 2 * TR * 128;     // 128*128 (reloaded up to 3x)
    int tid = threadIdx.x;
    int row0 = blockIdx.x * TR;
    {
        const float4* s4 = (const float4*)(g_agg + (size_t)row0 * HID);
        float4* d4 = (float4*)ins;
        for (int i = tid; i < TR * 32; i += NT) d4[i] = s4[i];
        const float4* W4 = (const float4*)W1;
        float4* Ws4 = (float4*)Ws;
        for (int i = tid; i < HID * 32; i += NT) Ws4[i] = W4[i];
    }
    __syncthreads();
    {
        GEMM_BODY4(ins, HID)
        float bb[8];
        #pragma unroll
        for (int c = 0; c < 8; c++) bb[c] = __ldg(&B1[cg * 8 + c]);
        #pragma unroll
        for (int r = 0; r < 4; r++)
            #pragma unroll
            for (int c = 0; c < 8; c++)
                act[(rg * 4 + r) * 128 + cg * 8 + c] = silu_f(acc[r][c] + bb[c]);
    }
    __syncthreads();
    {
        const float4* W4 = (const float4*)W2;
        float4* Ws4 = (float4*)Ws;
        for (int i = tid; i < HID * 32; i += NT) Ws4[i] = W4[i];
    }
    __syncthreads();
    {
        GEMM_BODY4(act, HID)
        float bb[8];
        #pragma unroll
        for (int c = 0; c < 8; c++) bb[c] = __ldg(&B2[cg * 8 + c]);
        #pragma unroll
        for (int r = 0; r < 4; r++) {
            int row = row0 + rg * 4 + r;
            const float* hp = g_h + (size_t)row * HID + cg * 8;
            #pragma unroll
            for (int c = 0; c < 8; c++)
                ins[(rg * 4 + r) * 128 + cg * 8 + c] = acc[r][c] + bb[c] + __ldg(&hp[c]);
        }
    }
    __syncthreads();

    // layernorm: 4 threads per row (32 rows), 32 ch each; write h_new to gmem AND ins
    {
        int r = tid >> 2, q = tid & 3;
        const float4* yr = (const float4*)(ins + r * 128 + q * 32);
        float s = 0.0f, ssq = 0.0f;
        float4 v[8];
        #pragma unroll
        for (int i = 0; i < 8; i++) {
            v[i] = yr[i];
            s   += v[i].x + v[i].y + v[i].z + v[i].w;
            ssq += v[i].x*v[i].x + v[i].y*v[i].y + v[i].z*v[i].z + v[i].w*v[i].w;
        }
        s   += __shfl_xor_sync(0xffffffffu, s, 1);
        ssq += __shfl_xor_sync(0xffffffffu, ssq, 1);
        s   += __shfl_xor_sync(0xffffffffu, s, 2);
        ssq += __shfl_xor_sync(0xffffffffu, ssq, 2);
        float mu = s * (1.0f / HID);
        float var = ssq * (1.0f / HID) - mu * mu;
        float rstd = rsqrtf(var + 1e-5f);
        float4* outp = (float4*)(g_h + (size_t)(row0 + r) * HID + q * 32);
        float4* insp = (float4*)(ins + r * 128 + q * 32);
        const float4* G4 = (const float4*)(G + q * 32);
        const float4* B4 = (const float4*)(Bt + q * 32);
        #pragma unroll
        for (int i = 0; i < 8; i++) {
            float4 gv = __ldg(&G4[i]);
            float4 bv = __ldg(&B4[i]);
            float4 o;
            o.x = (v[i].x - mu) * rstd * gv.x + bv.x;
            o.y = (v[i].y - mu) * rstd * gv.y + bv.y;
            o.z = (v[i].z - mu) * rstd * gv.z + bv.z;
            o.w = (v[i].w - mu) * rstd * gv.w + bv.w;
            outp[i] = o;
            insp[i] = o;
        }
    }

    if (!hasNext) return;

    // epilogue: x = h_new @ lin_in[next] (fp16 out); re-zero agg tile
    __syncthreads();
    {
        const float4* W4 = (const float4*)WlinNext;
        float4* Ws4 = (float4*)Ws;
        for (int i = tid; i < HID * 32; i += NT) Ws4[i] = W4[i];
    }
    __syncthreads();
    {
        GEMM_BODY4(ins, HID)
        #pragma unroll
        for (int r = 0; r < 4; r++) {
            __half2* dst = (__half2*)(g_x + (size_t)(row0 + rg * 4 + r) * HID + cg * 8);
            dst[0] = __floats2half2_rn(acc[r][0], acc[r][1]);
            dst[1] = __floats2half2_rn(acc[r][2], acc[r][3]);
            dst[2] = __floats2half2_rn(acc[r][4], acc[r][5]);
            dst[3] = __floats2half2_rn(acc[r][6], acc[r][7]);
        }
    }
    float4 z4 = {0.f, 0.f, 0.f, 0.f};
    float4* ag4 = (float4*)(g_agg + (size_t)row0 * HID);
    for (int i = tid; i < TR * 32; i += NT) ag4[i] = z4;
}

// ---------------------------------------------------------------- output zero + readout
__global__ void k_zero_out(float* out) {
    if (threadIdx.x < 64) out[threadIdx.x] = 0.0f;
}

__global__ void k_readout(const float* __restrict__ w1, const float* __restrict__ b1v,
                          const float* __restrict__ w2, const float* __restrict__ b2v,
                          float* __restrict__ out) {
    __shared__ float s[HID];
    __shared__ float part[2];
    int n = blockIdx.x, t = threadIdx.x;   // 64 threads
    float h0 = g_h[n * HID + t];
    float h1 = g_h[n * HID + 64 + t];
    s[t]      = silu_f(h0);
    s[64 + t] = silu_f(h1);
    __syncthreads();
    float a = b1v[t];
    #pragma unroll 8
    for (int k = 0; k < HID; k++) a += s[k] * w1[k * 64 + t];
    float v = silu_f(a) * w2[t];
    #pragma unroll
    for (int off = 16; off > 0; off >>= 1) v += __shfl_down_sync(0xffffffffu, v, off);
    if ((t & 31) == 0) part[t >> 5] = v;
    __syncthreads();
    if (t == 0) atomicAdd(&out[n >> 7], part[0] + part[1] + b2v[0]);
}

// ---------------------------------------------------------------- launch
extern "C" void kernel_launch(void* const* d_in, const int* in_sizes, int n_in,
                              void* d_out, int out_size) {
    const int*   Z       = (const int*)  d_in[0];
    const float* pos     = (const float*)d_in[1];
    const int*   ei      = (const int*)  d_in[2];
    const float* embed_w = (const float*)d_in[3];
    const float* ew1     = (const float*)d_in[4];
    const float* eb1     = (const float*)d_in[5];
    const float* ew2     = (const float*)d_in[6];
    const float* eb2     = (const float*)d_in[7];
    const float* linw    = (const float*)d_in[8];
    const float* nw1     = (const float*)d_in[9];
    const float* nb1     = (const float*)d_in[10];
    const float* nw2     = (const float*)d_in[11];
    const float* nb2     = (const float*)d_in[12];
    const float* lng     = (const float*)d_in[13];
    const float* lnb     = (const float*)d_in[14];
    const float* row1    = (const float*)d_in[15];
    const float* rob1    = (const float*)d_in[16];
    const float* row2    = (const float*)d_in[17];
    const float* rob2    = (const float*)d_in[18];
    float* out = (float*)d_out;

    const int SM_TABLE = (TR*64 + TR*128 + 128*128) * (int)sizeof(float);   // 88 KB
    const int SM_XGEMM = (TR*128 + 128*128) * (int)sizeof(float);           // 80 KB
    const int SM_NODE  = (2*TR*128 + 128*128) * (int)sizeof(float);         // 96 KB
    const int SM_EDGE  = TLEN * HID * 2;                                    // 128 KB
    cudaFuncSetAttribute(k_table_f, cudaFuncAttributeMaxDynamicSharedMemorySize, SM_TABLE);
    cudaFuncSetAttribute(k_xgemm_f, cudaFuncAttributeMaxDynamicSharedMemorySize, SM_XGEMM);
    cudaFuncSetAttribute(k_node_f,  cudaFuncAttributeMaxDynamicSharedMemorySize, SM_NODE);
    cudaFuncSetAttribute(k_edge_sm, cudaFuncAttributeMaxDynamicSharedMemorySize, SM_EDGE);

    k_dist<<<(NE + 255) / 256, 256>>>(ei, pos);
    dim3 tg(TLEN / TR, NBLK);
    k_table_f<<<tg, NT, SM_TABLE>>>(ew1, eb1, ew2, eb2);

    // prologue: embed -> h, x = h @ lin_in[0], zero agg
    k_xgemm_f<<<BN / TR, NT, SM_XGEMM>>>(linw, Z, embed_w);

    const int chunk = (NE + EBLK - 1) / EBLK;
    for (int b = 0; b < NBLK; b++) {
        k_edge_sm<<<EBLK, ETHR, SM_EDGE>>>(b, chunk);
        int hasNext = (b + 1 < NBLK) ? 1 : 0;
        const float* wnext = hasNext ? (linw + (b + 1) * HID * HID) : linw;
        k_node_f<<<BN / TR, NT, SM_NODE>>>(
            nw1 + b * HID * HID, nb1 + b * HID,
            nw2 + b * HID * HID, nb2 + b * HID,
            lng + b * HID, lnb + b * HID,
            wnext, hasNext);
    }

    k_zero_out<<<1, 64>>>(out);
    k_readout<<<BN, 64>>>(row1, rob1, row2, rob2, out);
}

// round 13
// speedup vs baseline: 1.3605x; 1.3605x over previous
#include <cuda_runtime.h>
#include <cuda_fp16.h>
#include <mma.h>
#include <math.h>

using namespace nvcuda;

#define BN    8192
#define HID   128
#define NE    262144
#define NRBF  64
#define NBLK  4
#define TLEN  512
#define RCUTF 6.0f
#define GAMMAF (10.0f/36.0f)
#define NT    128          // threads per GEMM block
#define TR    32           // rows per GEMM tile

// ---- scratch (device globals: allocation-free) ----
__device__ float  g_h[BN * HID];
__device__ __half g_x[BN * HID];                // fp16 x = h @ lin_in
__device__ float  g_agg[BN * HID];
__device__ int4   g_ep[NE];                     // packed edge: {u_bits, src, dst, 0}
__device__ __half g_tab[NBLK * TLEN * HID];     // 512 KB total; 128 KB per interaction block

__device__ __forceinline__ float silu_f(float v) { return v / (1.0f + expf(-v)); }

// ---------------------------------------------------------------- distances -> packed edge records
__global__ void k_dist(const int* __restrict__ ei, const float* __restrict__ pos) {
    int e = blockIdx.x * blockDim.x + threadIdx.x;
    if (e >= NE) return;
    int s = ei[e], d = ei[NE + e];
    float dx = pos[3*s]   - pos[3*d];
    float dy = pos[3*s+1] - pos[3*d+1];
    float dz = pos[3*s+2] - pos[3*d+2];
    float dd = sqrtf(dx*dx + dy*dy + dz*dz);
    dd = fminf(dd, RCUTF);
    float u = dd * ((float)(TLEN - 1) / RCUTF);
    g_ep[e] = make_int4(__float_as_int(u), s, d, 0);
}

// ================================================================
// FFMA GEMM tiles (table + prologue): 32 rows x 128 cols, 128 threads, 4x8 thread tile.
// ================================================================

#define GEMM_BODY4(SRC, KDIM)                                             \
    int cg = tid & 15, rg = tid >> 4;                                     \
    float acc[4][8];                                                      \
    _Pragma("unroll")                                                     \
    for (int r = 0; r < 4; r++)                                           \
        _Pragma("unroll")                                                 \
        for (int c = 0; c < 8; c++) acc[r][c] = 0.0f;                     \
    _Pragma("unroll 4")                                                   \
    for (int k = 0; k < KDIM; k++) {                                      \
        float4 w0 = ((const float4*)(Ws + k * 128))[cg * 2];              \
        float4 w1v = ((const float4*)(Ws + k * 128))[cg * 2 + 1];         \
        _Pragma("unroll")                                                 \
        for (int r = 0; r < 4; r++) {                                     \
            float a = SRC[(rg * 4 + r) * KDIM + k];                       \
            acc[r][0] += a * w0.x;  acc[r][1] += a * w0.y;                \
            acc[r][2] += a * w0.z;  acc[r][3] += a * w0.w;                \
            acc[r][4] += a * w1v.x; acc[r][5] += a * w1v.y;               \
            acc[r][6] += a * w1v.z; acc[r][7] += a * w1v.w;               \
        }                                                                 \
    }

// ---------------------------------------------------------------- tables: w_i(d), fp16 out
// grid (TLEN/32, NBLK), block 128; smem rbf[32*64] + act[32*128] + Ws[128*128] = 88 KB
__global__ void __launch_bounds__(NT, 2)
k_table_f(const float* __restrict__ w1, const float* __restrict__ b1,
          const float* __restrict__ w2, const float* __restrict__ b2) {
    extern __shared__ float sm[];
    float* rbfs = sm;                    // 32*64
    float* act  = sm + 32*64;            // 32*128
    float* Ws   = sm + 32*64 + 32*128;   // 128*128
    int tid = threadIdx.x;
    int blk = blockIdx.y;
    int t0  = blockIdx.x * TR;
    const float DSTEP = RCUTF / (float)(TLEN - 1);
    const float CSTEP = RCUTF / (float)(NRBF - 1);

    for (int i = tid; i < TR * 64; i += NT) {
        int row = i >> 6, c = i & 63;
        float d = (float)(t0 + row) * DSTEP;
        float u = d - (float)c * CSTEP;
        rbfs[i] = expf(-GAMMAF * u * u);
    }
    {
        const float4* W4 = (const float4*)(w1 + blk * NRBF * HID);
        float4* Ws4 = (float4*)Ws;
        for (int i = tid; i < NRBF * 32; i += NT) Ws4[i] = W4[i];
    }
    __syncthreads();

    {
        GEMM_BODY4(rbfs, NRBF)
        float bb[8];
        #pragma unroll
        for (int c = 0; c < 8; c++) bb[c] = __ldg(&b1[blk * HID + cg * 8 + c]);
        #pragma unroll
        for (int r = 0; r < 4; r++)
            #pragma unroll
            for (int c = 0; c < 8; c++)
                act[(rg * 4 + r) * 128 + cg * 8 + c] = silu_f(acc[r][c] + bb[c]);
    }
    __syncthreads();
    {
        const float4* W4 = (const float4*)(w2 + blk * HID * HID);
        float4* Ws4 = (float4*)Ws;
        for (int i = tid; i < HID * 32; i += NT) Ws4[i] = W4[i];
    }
    __syncthreads();
    {
        GEMM_BODY4(act, HID)
        float bb[8];
        #pragma unroll
        for (int c = 0; c < 8; c++) bb[c] = __ldg(&b2[blk * HID + cg * 8 + c]);
        #pragma unroll
        for (int r = 0; r < 4; r++) {
            __half2* dst = (__half2*)(g_tab + (size_t)(blk * TLEN + t0 + rg * 4 + r) * HID + cg * 8);
            dst[0] = __floats2half2_rn(acc[r][0] + bb[0], acc[r][1] + bb[1]);
            dst[1] = __floats2half2_rn(acc[r][2] + bb[2], acc[r][3] + bb[3]);
            dst[2] = __floats2half2_rn(acc[r][4] + bb[4], acc[r][5] + bb[5]);
            dst[3] = __floats2half2_rn(acc[r][6] + bb[6], acc[r][7] + bb[7]);
        }
    }
}

// ---------------------------------------------------------------- embed + x = h @ lin_in[0]; zero agg
// grid BN/32, block 128; smem hs[32*128] + Ws[128*128] = 80 KB
__global__ void __launch_bounds__(NT, 2)
k_xgemm_f(const float* __restrict__ W, const int* __restrict__ Z,
          const float* __restrict__ embed_w) {
    extern __shared__ float sm[];
    float* hs = sm;                   // 32*128
    float* Ws = sm + TR * 128;        // 128*128
    int tid = threadIdx.x;
    int row0 = blockIdx.x * TR;
    {
        float4* d4 = (float4*)hs;
        float4* h4 = (float4*)(g_h + (size_t)row0 * HID);
        for (int i = tid; i < TR * 32; i += NT) {
            int z = __ldg(&Z[row0 + (i >> 5)]);
            float4 v = __ldg(((const float4*)(embed_w + (size_t)z * HID)) + (i & 31));
            d4[i] = v;
            h4[i] = v;
        }
        const float4* W4 = (const float4*)W;
        float4* Ws4 = (float4*)Ws;
        for (int i = tid; i < HID * 32; i += NT) Ws4[i] = W4[i];
    }
    __syncthreads();
    GEMM_BODY4(hs, HID)
    #pragma unroll
    for (int r = 0; r < 4; r++) {
        __half2* dst = (__half2*)(g_x + (size_t)(row0 + rg * 4 + r) * HID + cg * 8);
        dst[0] = __floats2half2_rn(acc[r][0], acc[r][1]);
        dst[1] = __floats2half2_rn(acc[r][2], acc[r][3]);
        dst[2] = __floats2half2_rn(acc[r][4], acc[r][5]);
        dst[3] = __floats2half2_rn(acc[r][6], acc[r][7]);
    }
    float4 z4 = {0.f, 0.f, 0.f, 0.f};
    float4* ag4 = (float4*)(g_agg + (size_t)row0 * HID);
    for (int i = tid; i < TR * 32; i += NT) ag4[i] = z4;
}

// ---------------------------------------------------------------- edge scatter (R11 form: warp/edge, high occ)
// table via __ldg (L1), x via __ldcg (L2-only), packed record via __ldcs (streaming)
__global__ void k_edge(int blk) {
    int gid  = blockIdx.x * blockDim.x + threadIdx.x;
    int e    = gid >> 5;
    int lane = gid & 31;
    if (e >= NE) return;
    int4 ep = __ldcs(&g_ep[e]);
    float u = __int_as_float(ep.x);
    int i0 = (int)u;
    if (i0 > TLEN - 2) i0 = TLEN - 2;
    float f = u - (float)i0;
    const uint2* tb = (const uint2*)(g_tab + (size_t)blk * TLEN * HID);  // 32 uint2 per row
    uint2 ua = __ldg(tb + (size_t)i0 * 32 + lane);
    uint2 ub = __ldg(tb + (size_t)(i0 + 1) * 32 + lane);
    float2 a01 = __half22float2(*reinterpret_cast<const __half2*>(&ua.x));
    float2 a23 = __half22float2(*reinterpret_cast<const __half2*>(&ua.y));
    float2 b01 = __half22float2(*reinterpret_cast<const __half2*>(&ub.x));
    float2 b23 = __half22float2(*reinterpret_cast<const __half2*>(&ub.y));
    uint2 ux = __ldcg((const uint2*)(g_x + (size_t)ep.y * HID) + lane);
    float2 x01 = __half22float2(*reinterpret_cast<const __half2*>(&ux.x));
    float2 x23 = __half22float2(*reinterpret_cast<const __half2*>(&ux.y));
    float m0 = (a01.x + f * (b01.x - a01.x)) * x01.x;
    float m1 = (a01.y + f * (b01.y - a01.y)) * x01.y;
    float m2 = (a23.x + f * (b23.x - a23.x)) * x23.x;
    float m3 = (a23.y + f * (b23.y - a23.y)) * x23.y;
    float* ag = g_agg + (size_t)ep.z * HID + lane * 4;
    asm volatile("red.global.add.v4.f32 [%0], {%1, %2, %3, %4};"
                 :: "l"(ag), "f"(m0), "f"(m1), "f"(m2), "f"(m3) : "memory");
}

// ---------------------------------------------------------------- wmma node kernel
// block 128 threads (4 warps), tile 32 rows x 128 cols, K=128, m16n16k16 HMMA fp32-accum.
// smem: hA[32*128] fp16 (8K) + hW[128*128] fp16 (32K) + fO[32*128] fp32 (16K) = 56 KB
#define SM_NODE_BYTES (TR*HID*2 + HID*HID*2 + TR*HID*4)

// warp computes cols [warp*32, warp*32+32) over all 32 rows
__device__ __forceinline__ void wmma_gemm_32x128(const __half* hA, const __half* hW,
                                                 float* fO, int warp) {
    wmma::fragment<wmma::accumulator, 16, 16, 16, float> c[2][2];
    #pragma unroll
    for (int mt = 0; mt < 2; mt++)
        #pragma unroll
        for (int nt = 0; nt < 2; nt++)
            wmma::fill_fragment(c[mt][nt], 0.0f);
    #pragma unroll
    for (int k = 0; k < HID; k += 16) {
        wmma::fragment<wmma::matrix_a, 16, 16, 16, __half, wmma::row_major> a[2];
        wmma::load_matrix_sync(a[0], hA + 0 * 16 * HID + k, HID);
        wmma::load_matrix_sync(a[1], hA + 1 * 16 * HID + k, HID);
        wmma::fragment<wmma::matrix_b, 16, 16, 16, __half, wmma::row_major> b[2];
        wmma::load_matrix_sync(b[0], hW + (size_t)k * HID + warp * 32, HID);
        wmma::load_matrix_sync(b[1], hW + (size_t)k * HID + warp * 32 + 16, HID);
        #pragma unroll
        for (int mt = 0; mt < 2; mt++)
            #pragma unroll
            for (int nt = 0; nt < 2; nt++)
                wmma::mma_sync(c[mt][nt], a[mt], b[nt], c[mt][nt]);
    }
    #pragma unroll
    for (int mt = 0; mt < 2; mt++)
        #pragma unroll
        for (int nt = 0; nt < 2; nt++)
            wmma::store_matrix_sync(fO + (size_t)mt * 16 * HID + warp * 32 + nt * 16,
                                    c[mt][nt], HID, wmma::mem_row_major);
}

__device__ __forceinline__ void load_w_fp16(__half* hW, const float* W, int tid) {
    const float4* W4 = (const float4*)W;
    __half2* d = (__half2*)hW;
    for (int i = tid; i < HID * HID / 4; i += NT) {
        float4 v = W4[i];
        d[i * 2]     = __floats2half2_rn(v.x, v.y);
        d[i * 2 + 1] = __floats2half2_rn(v.z, v.w);
    }
}

__global__ void __launch_bounds__(NT, 2)
k_node_w(const float* __restrict__ W1, const float* __restrict__ B1,
         const float* __restrict__ W2, const float* __restrict__ B2,
         const float* __restrict__ G,  const float* __restrict__ Bt,
         const float* __restrict__ WlinNext, int hasNext) {
    extern __shared__ __align__(16) char smc[];
    __half* hA = (__half*)smc;                         // 32*128 fp16
    __half* hW = (__half*)(smc + TR * HID * 2);        // 128*128 fp16
    float*  fO = (float*)(smc + TR * HID * 2 + HID * HID * 2);  // 32*128 fp32
    int tid = threadIdx.x, warp = tid >> 5;
    int row0 = blockIdx.x * TR;

    // stage agg (fp32 -> fp16) and W1
    {
        const float4* a4 = (const float4*)(g_agg + (size_t)row0 * HID);
        __half2* d = (__half2*)hA;
        for (int i = tid; i < TR * 32; i += NT) {
            float4 v = a4[i];
            d[i * 2]     = __floats2half2_rn(v.x, v.y);
            d[i * 2 + 1] = __floats2half2_rn(v.z, v.w);
        }
        load_w_fp16(hW, W1, tid);
    }
    __syncthreads();
    wmma_gemm_32x128(hA, hW, fO, warp);
    __syncthreads();

    // act = silu(fO + B1) -> hA (fp16); load W2
    {
        const float4* o4 = (const float4*)fO;
        __half2* d = (__half2*)hA;
        for (int i = tid; i < TR * 32; i += NT) {
            float4 v = o4[i];
            float4 b = __ldg(((const float4*)B1) + (i & 31));
            float s0 = silu_f(v.x + b.x), s1 = silu_f(v.y + b.y);
            float s2 = silu_f(v.z + b.z), s3 = silu_f(v.w + b.w);
            d[i * 2]     = __floats2half2_rn(s0, s1);
            d[i * 2 + 1] = __floats2half2_rn(s2, s3);
        }
        load_w_fp16(hW, W2, tid);
    }
    __syncthreads();
    wmma_gemm_32x128(hA, hW, fO, warp);
    __syncthreads();

    // y = fO + B2 + h  (in place in fO)
    {
        float4* o4 = (float4*)fO;
        const float4* h4 = (const float4*)(g_h + (size_t)row0 * HID);
        for (int i = tid; i < TR * 32; i += NT) {
            float4 v = o4[i];
            float4 b = __ldg(((const float4*)B2) + (i & 31));
            float4 h = h4[i];
            v.x += b.x + h.x; v.y += b.y + h.y; v.z += b.z + h.z; v.w += b.w + h.w;
            o4[i] = v;
        }
    }
    __syncthreads();

    // layernorm: 4 threads per row, 32 ch each; write h_new to g_h AND hA (fp16)
    {
        int r = tid >> 2, q = tid & 3;
        const float4* yr = (const float4*)(fO + r * 128 + q * 32);
        float s = 0.0f, ssq = 0.0f;
        float4 v[8];
        #pragma unroll
        for (int i = 0; i < 8; i++) {
            v[i] = yr[i];
            s   += v[i].x + v[i].y + v[i].z + v[i].w;
            ssq += v[i].x*v[i].x + v[i].y*v[i].y + v[i].z*v[i].z + v[i].w*v[i].w;
        }
        s   += __shfl_xor_sync(0xffffffffu, s, 1);
        ssq += __shfl_xor_sync(0xffffffffu, ssq, 1);
        s   += __shfl_xor_sync(0xffffffffu, s, 2);
        ssq += __shfl_xor_sync(0xffffffffu, ssq, 2);
        float mu = s * (1.0f / HID);
        float var = ssq * (1.0f / HID) - mu * mu;
        float rstd = rsqrtf(var + 1e-5f);
        float4* outp = (float4*)(g_h + (size_t)(row0 + r) * HID + q * 32);
        __half2* hap = (__half2*)(hA + r * 128 + q * 32);
        const float4* G4 = (const float4*)(G + q * 32);
        const float4* B4 = (const float4*)(Bt + q * 32);
        #pragma unroll
        for (int i = 0; i < 8; i++) {
            float4 gv = __ldg(&G4[i]);
            float4 bv = __ldg(&B4[i]);
            float4 o;
            o.x = (v[i].x - mu) * rstd * gv.x + bv.x;
            o.y = (v[i].y - mu) * rstd * gv.y + bv.y;
            o.z = (v[i].z - mu) * rstd * gv.z + bv.z;
            o.w = (v[i].w - mu) * rstd * gv.w + bv.w;
            outp[i] = o;
            hap[i * 2]     = __floats2half2_rn(o.x, o.y);
            hap[i * 2 + 1] = __floats2half2_rn(o.z, o.w);
        }
    }

    if (!hasNext) return;

    load_w_fp16(hW, WlinNext, tid);
    __syncthreads();
    wmma_gemm_32x128(hA, hW, fO, warp);
    __syncthreads();

    // x = fO (fp16 out); re-zero agg tile
    {
        const float4* o4 = (const float4*)fO;
        __half2* xg = (__half2*)(g_x + (size_t)row0 * HID);
        for (int i = tid; i < TR * 32; i += NT) {
            float4 v = o4[i];
            xg[i * 2]     = __floats2half2_rn(v.x, v.y);
            xg[i * 2 + 1] = __floats2half2_rn(v.z, v.w);
        }
        float4 z4 = {0.f, 0.f, 0.f, 0.f};
        float4* ag4 = (float4*)(g_agg + (size_t)row0 * HID);
        for (int i = tid; i < TR * 32; i += NT) ag4[i] = z4;
    }
}

// ---------------------------------------------------------------- output zero + readout
__global__ void k_zero_out(float* out) {
    if (threadIdx.x < 64) out[threadIdx.x] = 0.0f;
}

__global__ void k_readout(const float* __restrict__ w1, const float* __restrict__ b1v,
                          const float* __restrict__ w2, const float* __restrict__ b2v,
                          float* __restrict__ out) {
    __shared__ float s[HID];
    __shared__ float part[2];
    int n = blockIdx.x, t = threadIdx.x;   // 64 threads
    float h0 = g_h[n * HID + t];
    float h1 = g_h[n * HID + 64 + t];
    s[t]      = silu_f(h0);
    s[64 + t] = silu_f(h1);
    __syncthreads();
    float a = b1v[t];
    #pragma unroll 8
    for (int k = 0; k < HID; k++) a += s[k] * w1[k * 64 + t];
    float v = silu_f(a) * w2[t];
    #pragma unroll
    for (int off = 16; off > 0; off >>= 1) v += __shfl_down_sync(0xffffffffu, v, off);
    if ((t & 31) == 0) part[t >> 5] = v;
    __syncthreads();
    if (t == 0) atomicAdd(&out[n >> 7], part[0] + part[1] + b2v[0]);
}

// ---------------------------------------------------------------- launch
extern "C" void kernel_launch(void* const* d_in, const int* in_sizes, int n_in,
                              void* d_out, int out_size) {
    const int*   Z       = (const int*)  d_in[0];
    const float* pos     = (const float*)d_in[1];
    const int*   ei      = (const int*)  d_in[2];
    const float* embed_w = (const float*)d_in[3];
    const float* ew1     = (const float*)d_in[4];
    const float* eb1     = (const float*)d_in[5];
    const float* ew2     = (const float*)d_in[6];
    const float* eb2     = (const float*)d_in[7];
    const float* linw    = (const float*)d_in[8];
    const float* nw1     = (const float*)d_in[9];
    const float* nb1     = (const float*)d_in[10];
    const float* nw2     = (const float*)d_in[11];
    const float* nb2     = (const float*)d_in[12];
    const float* lng     = (const float*)d_in[13];
    const float* lnb     = (const float*)d_in[14];
    const float* row1    = (const float*)d_in[15];
    const float* rob1    = (const float*)d_in[16];
    const float* row2    = (const float*)d_in[17];
    const float* rob2    = (const float*)d_in[18];
    float* out = (float*)d_out;

    const int SM_TABLE = (TR*64 + TR*128 + 128*128) * (int)sizeof(float);   // 88 KB
    const int SM_XGEMM = (TR*128 + 128*128) * (int)sizeof(float);           // 80 KB
    cudaFuncSetAttribute(k_table_f, cudaFuncAttributeMaxDynamicSharedMemorySize, SM_TABLE);
    cudaFuncSetAttribute(k_xgemm_f, cudaFuncAttributeMaxDynamicSharedMemorySize, SM_XGEMM);
    cudaFuncSetAttribute(k_node_w,  cudaFuncAttributeMaxDynamicSharedMemorySize, SM_NODE_BYTES);

    k_dist<<<(NE + 255) / 256, 256>>>(ei, pos);
    dim3 tg(TLEN / TR, NBLK);
    k_table_f<<<tg, NT, SM_TABLE>>>(ew1, eb1, ew2, eb2);

    // prologue: embed -> h, x = h @ lin_in[0], zero agg
    k_xgemm_f<<<BN / TR, NT, SM_XGEMM>>>(linw, Z, embed_w);

    for (int b = 0; b < NBLK; b++) {
        k_edge<<<NE / 8, 256>>>(b);
        int hasNext = (b + 1 < NBLK) ? 1 : 0;
        const float* wnext = hasNext ? (linw + (b + 1) * HID * HID) : linw;
        k_node_w<<<BN / TR, NT, SM_NODE_BYTES>>>(
            nw1 + b * HID * HID, nb1 + b * HID,
            nw2 + b * HID * HID, nb2 + b * HID,
            lng + b * HID, lnb + b * HID,
            wnext, hasNext);
    }

    k_zero_out<<<1, 64>>>(out);
    k_readout<<<BN, 64>>>(row1, rob1, row2, rob2, out);
}